// round 4
// baseline (speedup 1.0000x reference)
#include <cuda_runtime.h>
#include <math.h>

#define T_SEQ   512
#define IN_DIM  1024
#define H_DIM   2048
#define OUT_DIM 1024
#define GRID_P  148
#define NTHR    256
#define MAXR    14                          // ceil(2048/148)
#define SMEM_BYTES (2 * MAXR * H_DIM * 4)   // 229376 B dynamic: W_h2h1 + W_h2h2

// ---------------- device scratch (no allocation allowed) --------------------
__device__ float g_pre1[(size_t)T_SEQ * H_DIM];   // x@W_i2h1^T + b_i2h1 + b_h2h1
__device__ float g_h1[2][H_DIM];
__device__ float g_h2[2][H_DIM];
__device__ unsigned g_arrive[GRID_P * 8];         // padded arrival flags (32B apart)

__device__ __forceinline__ float dot4(float4 a, float4 b) {
    return a.x * b.x + a.y * b.y + a.z * b.z + a.w * b.w;
}

// Atomic-free grid barrier: per-CTA release-store to its own flag slot
// (parallel, no L2 atomic serialization); every CTA polls all flags directly
// (threads 0..147, one flag each) -- no central checker, no broadcast hop.
// Flags increase monotonically; reset by pre_gemm each replay.
__device__ __forceinline__ void grid_bar(unsigned target) {
    __syncthreads();
    if (threadIdx.x == 0) {
        asm volatile("st.release.gpu.u32 [%0], %1;"
                     :: "l"(&g_arrive[blockIdx.x * 8]), "r"(target) : "memory");
    }
    if (threadIdx.x < GRID_P) {
        unsigned v;
        do {
            asm volatile("ld.acquire.gpu.u32 %0, [%1];"
                         : "=r"(v) : "l"(&g_arrive[threadIdx.x * 8]) : "memory");
        } while (v < target);
    }
    __syncthreads();
}

// ---------------------------------------------------------------------------
// Kernel 1: pre1[t][j] = x[t] @ W_i2h1[j] + b_i2h1[j] + b_h2h1[j]
// ---------------------------------------------------------------------------
#define BT 64
#define BJ 128
#define BK 32

__global__ __launch_bounds__(128) void pre_gemm(
    const float* __restrict__ X, const float* __restrict__ W,
    const float* __restrict__ b1, const float* __restrict__ b2)
{
    // reset barrier flags for the persistent kernel (each replay)
    if (blockIdx.x == 0 && blockIdx.y == 0 && threadIdx.x < GRID_P)
        g_arrive[threadIdx.x * 8] = 0;

    __shared__ float Xs[BT][BK + 1];
    __shared__ float Ws[BJ][BK + 1];
    const int tid = threadIdx.x;
    const int bt = blockIdx.y * BT;
    const int bj = blockIdx.x * BJ;
    const int tx = tid & 15;
    const int ty = tid >> 4;

    float acc[8][8];
#pragma unroll
    for (int i = 0; i < 8; i++)
#pragma unroll
        for (int j = 0; j < 8; j++) acc[i][j] = 0.f;

    for (int k0 = 0; k0 < IN_DIM; k0 += BK) {
#pragma unroll
        for (int i = tid; i < BT * (BK / 4); i += 128) {
            int t = i / (BK / 4), kq = i % (BK / 4);
            float4 v = *(const float4*)(X + (size_t)(bt + t) * IN_DIM + k0 + kq * 4);
            Xs[t][kq * 4 + 0] = v.x; Xs[t][kq * 4 + 1] = v.y;
            Xs[t][kq * 4 + 2] = v.z; Xs[t][kq * 4 + 3] = v.w;
        }
#pragma unroll
        for (int i = tid; i < BJ * (BK / 4); i += 128) {
            int j = i / (BK / 4), kq = i % (BK / 4);
            float4 v = *(const float4*)(W + (size_t)(bj + j) * IN_DIM + k0 + kq * 4);
            Ws[j][kq * 4 + 0] = v.x; Ws[j][kq * 4 + 1] = v.y;
            Ws[j][kq * 4 + 2] = v.z; Ws[j][kq * 4 + 3] = v.w;
        }
        __syncthreads();
#pragma unroll 8
        for (int kk = 0; kk < BK; kk++) {
            float a[8], b[8];
#pragma unroll
            for (int i = 0; i < 8; i++) a[i] = Xs[ty * 8 + i][kk];
#pragma unroll
            for (int j = 0; j < 8; j++) b[j] = Ws[tx * 8 + j][kk];
#pragma unroll
            for (int i = 0; i < 8; i++)
#pragma unroll
                for (int j = 0; j < 8; j++) acc[i][j] += a[i] * b[j];
        }
        __syncthreads();
    }
#pragma unroll
    for (int i = 0; i < 8; i++) {
        int t = bt + ty * 8 + i;
#pragma unroll
        for (int j = 0; j < 8; j++) {
            int col = bj + tx * 8 + j;
            g_pre1[(size_t)t * H_DIM + col] = acc[i][j] + __ldg(b1 + col) + __ldg(b2 + col);
        }
    }
}

// ---------------------------------------------------------------------------
// Kernel 2: persistent RNN, FUSED phases. Between consecutive barriers we
// compute BOTH h2(t) (layer 2) and h1(t+1) (layer 1 of the next step) from
// the single post-barrier load of h1(t), h2(t-1). Exactly one grid barrier
// per step. Stage-1: 4 xor-shuffles -> 2 partials/warp -> red[28][16].
// Stage-2: 8 threads/row over 28 rows (tid<224), width-8 shfl_down.
// ---------------------------------------------------------------------------
__global__ __launch_bounds__(NTHR, 1) void rnn_persistent(
    const float* __restrict__ W_h2h1,
    const float* __restrict__ W_i2h2,
    const float* __restrict__ b_i2h2,
    const float* __restrict__ W_h2h2,
    const float* __restrict__ b_h2h2)
{
    extern __shared__ float smem[];
    float* Wsh1 = smem;                    // [MAXR][2048]
    float* Wsh2 = smem + MAXR * H_DIM;     // [MAXR][2048]
    __shared__ __align__(8) float red[2 * MAXR][16];   // 1792B
    __shared__ float bsum[MAXR];

    const int tid = threadIdx.x;
    const int bid = blockIdx.x;
    const int r0 = (bid * H_DIM) / GRID_P;
    const int r1 = ((bid + 1) * H_DIM) / GRID_P;
    const int nr = r1 - r0;                // 13 or 14
    const int lane = tid & 31;
    const int wid = tid >> 5;

    // h1(0) = tanh(pre1[0]) (h1(-1)=0); h2(-1) = 0 lives in g_h2[1]
    if (tid < nr) {
        g_h1[0][r0 + tid] = tanhf(__ldg(&g_pre1[r0 + tid]));
        g_h2[1][r0 + tid] = 0.f;
        bsum[tid] = __ldg(b_i2h2 + r0 + tid) + __ldg(b_h2h2 + r0 + tid);
    }

    // SMEM weight caches (own rows of W_h2h1, W_h2h2)
    {
        const float4* s1 = (const float4*)(W_h2h1 + (size_t)r0 * H_DIM);
        const float4* s2 = (const float4*)(W_h2h2 + (size_t)r0 * H_DIM);
        float4* d1 = (float4*)Wsh1;
        float4* d2 = (float4*)Wsh2;
        const int n4 = nr * (H_DIM / 4);
        for (int i = tid; i < n4; i += NTHR) { d1[i] = s1[i]; d2[i] = s2[i]; }
    }

    // Register-stationary W_i2h2 slices (cols 4*tid.. and 1024+4*tid..)
    float4 wr0[MAXR], wr1[MAXR];
#pragma unroll
    for (int rr = 0; rr < MAXR; rr++) {
        int r = (rr < nr) ? (r0 + rr) : r0;
        const float4* wp = (const float4*)(W_i2h2 + (size_t)r * H_DIM);
        wr0[rr] = wp[tid];
        wr1[rr] = wp[tid + 256];
    }

    unsigned tgt = 1;
    grid_bar(tgt);                         // h1(0), h2(-1), caches visible

    const int frow = tid >> 3;             // stage-2 row (0..31)
    const int fs = tid & 7;                // stage-2 sub-index
    // clamped prefetch row for the A-part (rows 14..27 -> pre1 row)
    const int prowA = (frow >= MAXR) ? (((frow - MAXR) < nr) ? (frow - MAXR) : (nr - 1)) : 0;

    for (int t = 0; t < T_SEQ - 1; t++) {
        const int q = t & 1;

        // prefetch pre1[t+1] for the A rows
        float pre = __ldg(&g_pre1[(size_t)(t + 1) * H_DIM + r0 + prowA]);

        // single post-barrier load: h1(t) and h2(t-1) slices
        float4 n0 = __ldcg((const float4*)g_h1[q] + tid);
        float4 n1 = __ldcg((const float4*)g_h1[q] + tid + 256);
        float4 c0 = __ldcg((const float4*)g_h2[1 - q] + tid);
        float4 c1 = __ldcg((const float4*)g_h2[1 - q] + tid + 256);

        // ---- fused stage-1: accB -> h2(t) rows, accA -> h1(t+1) rows ----
#pragma unroll
        for (int rr = 0; rr < MAXR; rr++) {
            const float* w1 = Wsh1 + rr * H_DIM;
            const float* w2 = Wsh2 + rr * H_DIM;
            float4 w10 = *(const float4*)(w1 + 4 * tid);
            float4 w11 = *(const float4*)(w1 + 4 * tid + 1024);
            float4 w20 = *(const float4*)(w2 + 4 * tid);
            float4 w21 = *(const float4*)(w2 + 4 * tid + 1024);
            float accA = dot4(w10, n0) + dot4(w11, n1);
            float accB = dot4(wr0[rr], n0) + dot4(wr1[rr], n1)
                       + dot4(w20, c0) + dot4(w21, c1);
            accA += __shfl_xor_sync(0xffffffffu, accA, 16);
            accB += __shfl_xor_sync(0xffffffffu, accB, 16);
            accA += __shfl_xor_sync(0xffffffffu, accA, 8);
            accB += __shfl_xor_sync(0xffffffffu, accB, 8);
            accA += __shfl_xor_sync(0xffffffffu, accA, 4);
            accB += __shfl_xor_sync(0xffffffffu, accB, 4);
            accA += __shfl_xor_sync(0xffffffffu, accA, 2);
            accB += __shfl_xor_sync(0xffffffffu, accB, 2);
            if (lane < 2) {
                red[rr][wid * 2 + lane] = accB;          // even/odd partials
                red[MAXR + rr][wid * 2 + lane] = accA;
            }
        }
        __syncthreads();

        // ---- stage-2: 28 rows x 8 threads ----
        if (tid < 224) {
            float2 v = *(const float2*)&red[frow][fs * 2];
            float x = v.x + v.y;
            x += __shfl_down_sync(0xffffffffu, x, 4, 8);
            x += __shfl_down_sync(0xffffffffu, x, 2, 8);
            x += __shfl_down_sync(0xffffffffu, x, 1, 8);
            if (fs == 0) {
                if (frow < MAXR) {                       // B: h2(t)
                    if (frow < nr)
                        g_h2[q][r0 + frow] = tanhf(bsum[frow] + x);
                } else {                                 // A: h1(t+1)
                    int ar = frow - MAXR;
                    if (ar < nr)
                        g_h1[1 - q][r0 + ar] = tanhf(pre + x);
                }
            }
        }
        grid_bar(++tgt);   // the ONLY grid barrier of the step
    }

    // ---- epilogue t = 511: h2(511) only ----
    {
        float4 n0 = __ldcg((const float4*)g_h1[1] + tid);
        float4 n1 = __ldcg((const float4*)g_h1[1] + tid + 256);
        float4 c0 = __ldcg((const float4*)g_h2[0] + tid);
        float4 c1 = __ldcg((const float4*)g_h2[0] + tid + 256);
#pragma unroll
        for (int rr = 0; rr < MAXR; rr++) {
            const float* w2 = Wsh2 + rr * H_DIM;
            float4 w20 = *(const float4*)(w2 + 4 * tid);
            float4 w21 = *(const float4*)(w2 + 4 * tid + 1024);
            float accB = dot4(wr0[rr], n0) + dot4(wr1[rr], n1)
                       + dot4(w20, c0) + dot4(w21, c1);
            accB += __shfl_xor_sync(0xffffffffu, accB, 16);
            accB += __shfl_xor_sync(0xffffffffu, accB, 8);
            accB += __shfl_xor_sync(0xffffffffu, accB, 4);
            accB += __shfl_xor_sync(0xffffffffu, accB, 2);
            if (lane < 2) red[rr][wid * 2 + lane] = accB;
        }
        __syncthreads();
        if (tid < 224) {
            float2 v = *(const float2*)&red[frow][fs * 2];
            float x = v.x + v.y;
            x += __shfl_down_sync(0xffffffffu, x, 4, 8);
            x += __shfl_down_sync(0xffffffffu, x, 2, 8);
            x += __shfl_down_sync(0xffffffffu, x, 1, 8);
            if (fs == 0 && frow < nr)
                g_h2[1][r0 + frow] = tanhf(bsum[frow] + x);
        }
    }
    // final h2 (t=511) is in g_h2[1]; kernel boundary publishes it
}

// ---------------------------------------------------------------------------
// Kernel 3: out = h2_final @ W_h2o2^T + b_h2o2
// ---------------------------------------------------------------------------
__global__ __launch_bounds__(256) void out_gemv(
    const float* __restrict__ W, const float* __restrict__ b,
    float* __restrict__ out)
{
    const int lane = threadIdx.x & 31;
    const int warp = threadIdx.x >> 5;
    const int row = blockIdx.x * 8 + warp;
    const float4* wp = (const float4*)(W + (size_t)row * H_DIM);
    const float4* hp = (const float4*)g_h2[1];
    float acc = 0.f;
#pragma unroll
    for (int i = 0; i < 16; i++) {
        float4 w4 = __ldg(wp + i * 32 + lane);
        float4 h4 = __ldcg(hp + i * 32 + lane);
        acc += dot4(w4, h4);
    }
#pragma unroll
    for (int off = 16; off; off >>= 1)
        acc += __shfl_xor_sync(0xffffffffu, acc, off);
    if (lane == 0) out[row] = acc + __ldg(b + row);
}

// ---------------------------------------------------------------------------
extern "C" void kernel_launch(void* const* d_in, const int* in_sizes, int n_in,
                              void* d_out, int out_size)
{
    const float* word   = (const float*)d_in[0];
    const float* W_i2h1 = (const float*)d_in[1];
    const float* b_i2h1 = (const float*)d_in[2];
    const float* W_h2h1 = (const float*)d_in[3];
    const float* b_h2h1 = (const float*)d_in[4];
    // d_in[5], d_in[6]: W_h2o1 / b_h2o1 — dead code in reference
    const float* W_i2h2 = (const float*)d_in[7];
    const float* b_i2h2 = (const float*)d_in[8];
    const float* W_h2h2 = (const float*)d_in[9];
    const float* b_h2h2 = (const float*)d_in[10];
    const float* W_h2o2 = (const float*)d_in[11];
    const float* b_h2o2 = (const float*)d_in[12];
    float* out = (float*)d_out;

    cudaFuncSetAttribute(rnn_persistent,
                         cudaFuncAttributeMaxDynamicSharedMemorySize, SMEM_BYTES);

    dim3 pg(H_DIM / BJ, T_SEQ / BT);
    pre_gemm<<<pg, 128>>>(word, W_i2h1, b_i2h1, b_h2h1);
    rnn_persistent<<<GRID_P, NTHR, SMEM_BYTES>>>(W_h2h1, W_i2h2, b_i2h2,
                                                 W_h2h2, b_h2h2);
    out_gemv<<<OUT_DIM / 8, 256>>>(W_h2o2, b_h2o2, out);
}

// round 6
// speedup vs baseline: 1.2802x; 1.2802x over previous
#include <cuda_runtime.h>
#include <math.h>

#define T_SEQ   512
#define IN_DIM  1024
#define H_DIM   2048
#define OUT_DIM 1024
#define GRID_P  148
#define NTHR    256
#define MAXR    14                          // ceil(2048/148)
#define SMEM_BYTES (2 * MAXR * H_DIM * 4)   // 229376 B dynamic: W_h2h1 + W_h2h2

// ---------------- device scratch (no allocation allowed) --------------------
__device__ float g_pre1[(size_t)T_SEQ * H_DIM];   // x@W_i2h1^T + b_i2h1 + b_h2h1
__device__ float g_h1[2][H_DIM];
__device__ float g_h2[2][H_DIM];
__device__ unsigned g_bar_ctr;                    // monotonic arrival counter

__device__ __forceinline__ float dot4(float4 a, float4 b) {
    return a.x * b.x + a.y * b.y + a.z * b.z + a.w * b.w;
}

// Grid barrier, return-free arrive: red.add (REDG, ~0.85 cyc/op at L2 -- no
// return-path serialization like atom.add) + acquire spin on ONE hot line.
// Counter is monotonic: barrier k waits for ctr >= k*GRID_P. Release on the
// red orders each CTA's h-stores before its increment; acquire on the load +
// the RMW release sequence makes all 148 CTAs' stores visible to waiters.
// Reset to 0 by pre_gemm on every replay.
__device__ __forceinline__ void grid_bar(unsigned target) {
    __syncthreads();
    if (threadIdx.x == 0) {
        asm volatile("red.release.gpu.add.u32 [%0], %1;"
                     :: "l"(&g_bar_ctr), "r"(1u) : "memory");
        unsigned v;
        do {
            asm volatile("ld.acquire.gpu.u32 %0, [%1];"
                         : "=r"(v) : "l"(&g_bar_ctr) : "memory");
        } while (v < target);
    }
    __syncthreads();
}

// ---------------------------------------------------------------------------
// Kernel 1: pre1[t][j] = x[t] @ W_i2h1[j] + b_i2h1[j] + b_h2h1[j]
// ---------------------------------------------------------------------------
#define BT 64
#define BJ 128
#define BK 32

__global__ __launch_bounds__(128) void pre_gemm(
    const float* __restrict__ X, const float* __restrict__ W,
    const float* __restrict__ b1, const float* __restrict__ b2)
{
    // reset barrier counter for the persistent kernel (each replay)
    if (blockIdx.x == 0 && blockIdx.y == 0 && threadIdx.x == 0)
        g_bar_ctr = 0;

    __shared__ float Xs[BT][BK + 1];
    __shared__ float Ws[BJ][BK + 1];
    const int tid = threadIdx.x;
    const int bt = blockIdx.y * BT;
    const int bj = blockIdx.x * BJ;
    const int tx = tid & 15;
    const int ty = tid >> 4;

    float acc[8][8];
#pragma unroll
    for (int i = 0; i < 8; i++)
#pragma unroll
        for (int j = 0; j < 8; j++) acc[i][j] = 0.f;

    for (int k0 = 0; k0 < IN_DIM; k0 += BK) {
#pragma unroll
        for (int i = tid; i < BT * (BK / 4); i += 128) {
            int t = i / (BK / 4), kq = i % (BK / 4);
            float4 v = *(const float4*)(X + (size_t)(bt + t) * IN_DIM + k0 + kq * 4);
            Xs[t][kq * 4 + 0] = v.x; Xs[t][kq * 4 + 1] = v.y;
            Xs[t][kq * 4 + 2] = v.z; Xs[t][kq * 4 + 3] = v.w;
        }
#pragma unroll
        for (int i = tid; i < BJ * (BK / 4); i += 128) {
            int j = i / (BK / 4), kq = i % (BK / 4);
            float4 v = *(const float4*)(W + (size_t)(bj + j) * IN_DIM + k0 + kq * 4);
            Ws[j][kq * 4 + 0] = v.x; Ws[j][kq * 4 + 1] = v.y;
            Ws[j][kq * 4 + 2] = v.z; Ws[j][kq * 4 + 3] = v.w;
        }
        __syncthreads();
#pragma unroll 8
        for (int kk = 0; kk < BK; kk++) {
            float a[8], b[8];
#pragma unroll
            for (int i = 0; i < 8; i++) a[i] = Xs[ty * 8 + i][kk];
#pragma unroll
            for (int j = 0; j < 8; j++) b[j] = Ws[tx * 8 + j][kk];
#pragma unroll
            for (int i = 0; i < 8; i++)
#pragma unroll
                for (int j = 0; j < 8; j++) acc[i][j] += a[i] * b[j];
        }
        __syncthreads();
    }
#pragma unroll
    for (int i = 0; i < 8; i++) {
        int t = bt + ty * 8 + i;
#pragma unroll
        for (int j = 0; j < 8; j++) {
            int col = bj + tx * 8 + j;
            g_pre1[(size_t)t * H_DIM + col] = acc[i][j] + __ldg(b1 + col) + __ldg(b2 + col);
        }
    }
}

// ---------------------------------------------------------------------------
// Kernel 2: persistent RNN (R3 structure). One grid barrier per step (after
// phase A). Stage-1: 3 xor-shuffles -> 4 partials/warp -> red[row][32].
// Stage-2: 8 threads/row, float4 + width-8 shfl_down.
// ---------------------------------------------------------------------------
__global__ __launch_bounds__(NTHR, 1) void rnn_persistent(
    const float* __restrict__ W_h2h1,
    const float* __restrict__ W_i2h2,
    const float* __restrict__ b_i2h2,
    const float* __restrict__ W_h2h2,
    const float* __restrict__ b_h2h2)
{
    extern __shared__ float smem[];
    float* Wsh1 = smem;                    // [MAXR][2048]
    float* Wsh2 = smem + MAXR * H_DIM;     // [MAXR][2048]
    __shared__ __align__(16) float red[16][32];   // 2KB, single buffer
    __shared__ float bsum[16];

    const int tid = threadIdx.x;
    const int bid = blockIdx.x;
    const int r0 = (bid * H_DIM) / GRID_P;
    const int r1 = ((bid + 1) * H_DIM) / GRID_P;
    const int nr = r1 - r0;                // 13 or 14
    const int lane = tid & 31;
    const int wid = tid >> 5;

    // init h2 odd buffer (phase B of t=0 reads g_h2[1]); fused layer-2 bias
    if (tid < nr) {
        g_h2[1][r0 + tid] = 0.f;
        bsum[tid] = __ldg(b_i2h2 + r0 + tid) + __ldg(b_h2h2 + r0 + tid);
    }

    // SMEM weight caches (own rows of W_h2h1, W_h2h2)
    {
        const float4* s1 = (const float4*)(W_h2h1 + (size_t)r0 * H_DIM);
        const float4* s2 = (const float4*)(W_h2h2 + (size_t)r0 * H_DIM);
        float4* d1 = (float4*)Wsh1;
        float4* d2 = (float4*)Wsh2;
        const int n4 = nr * (H_DIM / 4);
        for (int i = tid; i < n4; i += NTHR) { d1[i] = s1[i]; d2[i] = s2[i]; }
    }

    // Register-stationary W_i2h2 slices (cols 4*tid.. and 1024+4*tid..)
    float4 wr0[MAXR], wr1[MAXR];
#pragma unroll
    for (int rr = 0; rr < MAXR; rr++) {
        int r = (rr < nr) ? (r0 + rr) : r0;
        const float4* wp = (const float4*)(W_i2h2 + (size_t)r * H_DIM);
        wr0[rr] = wp[tid];
        wr1[rr] = wp[tid + 256];
    }

    unsigned tgt = GRID_P;
    grid_bar(tgt);

    const int frow = tid >> 3;             // stage-2 row (0..31 for tid<256)
    const int fs = tid & 7;                // stage-2 float4 index
    const int prow = (frow < nr) ? frow : (nr - 1);   // clamped prefetch row

    float4 a0 = make_float4(0.f, 0.f, 0.f, 0.f), a1 = a0;   // h1(t-1) slice

    for (int t = 0; t < T_SEQ; t++) {
        const int q = t & 1;

        // protect red[] against previous iteration's phase-B stage-2 reads
        __syncthreads();

        // ---- phase A: h1(t) = tanh(pre1[t] + W_h2h1 @ h1(t-1)) ----
        float pre = __ldg(&g_pre1[(size_t)t * H_DIM + r0 + prow]);  // prefetch
#pragma unroll
        for (int rr = 0; rr < MAXR; rr++) {
            const float* w = Wsh1 + rr * H_DIM;
            float4 w0 = *(const float4*)(w + 4 * tid);
            float4 w1 = *(const float4*)(w + 4 * tid + 1024);
            float acc = dot4(w0, a0) + dot4(w1, a1);
            acc += __shfl_xor_sync(0xffffffffu, acc, 16);
            acc += __shfl_xor_sync(0xffffffffu, acc, 8);
            acc += __shfl_xor_sync(0xffffffffu, acc, 4);
            if (lane < 4) red[rr][wid * 4 + lane] = acc;
        }
        __syncthreads();
        if (tid < 128) {                    // 4 full warps
            float4 v = *((const float4*)red[frow] + fs);
            float x = (v.x + v.y) + (v.z + v.w);
            x += __shfl_down_sync(0xffffffffu, x, 4, 8);
            x += __shfl_down_sync(0xffffffffu, x, 2, 8);
            x += __shfl_down_sync(0xffffffffu, x, 1, 8);
            if (fs == 0 && frow < nr)
                g_h1[q][r0 + frow] = tanhf(pre + x);
        }
        tgt += GRID_P;
        grid_bar(tgt);      // the ONLY grid barrier of the step

        // ---- phase B: h2(t) = tanh(W_i2h2@h1(t) + W_h2h2@h2(t-1) + b) ----
        float4 n0 = __ldcg((const float4*)g_h1[q] + tid);
        float4 n1 = __ldcg((const float4*)g_h1[q] + tid + 256);
        float4 c0 = __ldcg((const float4*)g_h2[1 - q] + tid);
        float4 c1 = __ldcg((const float4*)g_h2[1 - q] + tid + 256);
#pragma unroll
        for (int rr = 0; rr < MAXR; rr++) {
            const float* w = Wsh2 + rr * H_DIM;
            float4 w0 = *(const float4*)(w + 4 * tid);
            float4 w1 = *(const float4*)(w + 4 * tid + 1024);
            float acc = dot4(wr0[rr], n0) + dot4(wr1[rr], n1)
                      + dot4(w0, c0) + dot4(w1, c1);
            acc += __shfl_xor_sync(0xffffffffu, acc, 16);
            acc += __shfl_xor_sync(0xffffffffu, acc, 8);
            acc += __shfl_xor_sync(0xffffffffu, acc, 4);
            if (lane < 4) red[rr][wid * 4 + lane] = acc;
        }
        __syncthreads();
        if (tid < 128) {
            float4 v = *((const float4*)red[frow] + fs);
            float x = (v.x + v.y) + (v.z + v.w);
            x += __shfl_down_sync(0xffffffffu, x, 4, 8);
            x += __shfl_down_sync(0xffffffffu, x, 2, 8);
            x += __shfl_down_sync(0xffffffffu, x, 1, 8);
            if (fs == 0 && frow < nr)
                g_h2[q][r0 + frow] = tanhf(bsum[frow] + x);
        }
        a0 = n0; a1 = n1;   // h1(t) slice becomes next step's h1(t-1)
        // no end-of-step barrier: next step's post-A barrier orders everything
    }
    // final h2 (t=511, q=1) is in g_h2[1]
}

// ---------------------------------------------------------------------------
// Kernel 3: out = h2_final @ W_h2o2^T + b_h2o2
// ---------------------------------------------------------------------------
__global__ __launch_bounds__(256) void out_gemv(
    const float* __restrict__ W, const float* __restrict__ b,
    float* __restrict__ out)
{
    const int lane = threadIdx.x & 31;
    const int warp = threadIdx.x >> 5;
    const int row = blockIdx.x * 8 + warp;
    const float4* wp = (const float4*)(W + (size_t)row * H_DIM);
    const float4* hp = (const float4*)g_h2[1];
    float acc = 0.f;
#pragma unroll
    for (int i = 0; i < 16; i++) {
        float4 w4 = __ldg(wp + i * 32 + lane);
        float4 h4 = __ldcg(hp + i * 32 + lane);
        acc += dot4(w4, h4);
    }
#pragma unroll
    for (int off = 16; off; off >>= 1)
        acc += __shfl_xor_sync(0xffffffffu, acc, off);
    if (lane == 0) out[row] = acc + __ldg(b + row);
}

// ---------------------------------------------------------------------------
extern "C" void kernel_launch(void* const* d_in, const int* in_sizes, int n_in,
                              void* d_out, int out_size)
{
    const float* word   = (const float*)d_in[0];
    const float* W_i2h1 = (const float*)d_in[1];
    const float* b_i2h1 = (const float*)d_in[2];
    const float* W_h2h1 = (const float*)d_in[3];
    const float* b_h2h1 = (const float*)d_in[4];
    // d_in[5], d_in[6]: W_h2o1 / b_h2o1 — dead code in reference
    const float* W_i2h2 = (const float*)d_in[7];
    const float* b_i2h2 = (const float*)d_in[8];
    const float* W_h2h2 = (const float*)d_in[9];
    const float* b_h2h2 = (const float*)d_in[10];
    const float* W_h2o2 = (const float*)d_in[11];
    const float* b_h2o2 = (const float*)d_in[12];
    float* out = (float*)d_out;

    cudaFuncSetAttribute(rnn_persistent,
                         cudaFuncAttributeMaxDynamicSharedMemorySize, SMEM_BYTES);

    dim3 pg(H_DIM / BJ, T_SEQ / BT);
    pre_gemm<<<pg, 128>>>(word, W_i2h1, b_i2h1, b_h2h1);
    rnn_persistent<<<GRID_P, NTHR, SMEM_BYTES>>>(W_h2h1, W_i2h2, b_i2h2,
                                                 W_h2h2, b_h2h2);
    out_gemv<<<OUT_DIM / 8, 256>>>(W_h2o2, b_h2o2, out);
}

// round 7
// speedup vs baseline: 1.4498x; 1.1324x over previous
#include <cuda_runtime.h>
#include <math.h>

#define T_SEQ   512
#define IN_DIM  1024
#define H_DIM   2048
#define OUT_DIM 1024
#define GRID_P  148
#define NTHR    256
#define MAXR    14                          // ceil(2048/148)
#define SMEM_BYTES (2 * MAXR * H_DIM * 4)   // 229376 B dynamic: W_h2h1 + W_h2h2

// ---------------- device scratch (no allocation allowed) --------------------
__device__ float g_pre1[(size_t)T_SEQ * H_DIM];   // x@W_i2h1^T + b_i2h1 + b_h2h1
__device__ float g_h1[2][H_DIM];
__device__ float g_h2[2][H_DIM];
__device__ unsigned g_bar_ctr;                    // monotonic arrival counter

__device__ __forceinline__ float dot4(float4 a, float4 b) {
    return a.x * b.x + a.y * b.y + a.z * b.z + a.w * b.w;
}

// Grid barrier, return-free arrive: red.release.gpu.add (no return-path
// serialization) + acquire spin on the single counter line. Monotonic:
// barrier k waits for ctr >= k*GRID_P. Reset by pre_gemm each replay.
__device__ __forceinline__ void grid_bar(unsigned target) {
    __syncthreads();
    if (threadIdx.x == 0) {
        asm volatile("red.release.gpu.add.u32 [%0], %1;"
                     :: "l"(&g_bar_ctr), "r"(1u) : "memory");
        unsigned v;
        do {
            asm volatile("ld.acquire.gpu.u32 %0, [%1];"
                         : "=r"(v) : "l"(&g_bar_ctr) : "memory");
        } while (v < target);
    }
    __syncthreads();
}

// ---------------------------------------------------------------------------
// Kernel 1: pre1[t][j] = x[t] @ W_i2h1[j] + b_i2h1[j] + b_h2h1[j]
// ---------------------------------------------------------------------------
#define BT 64
#define BJ 128
#define BK 32

__global__ __launch_bounds__(128) void pre_gemm(
    const float* __restrict__ X, const float* __restrict__ W,
    const float* __restrict__ b1, const float* __restrict__ b2)
{
    // reset barrier counter for the persistent kernel (each replay)
    if (blockIdx.x == 0 && blockIdx.y == 0 && threadIdx.x == 0)
        g_bar_ctr = 0;

    __shared__ float Xs[BT][BK + 1];
    __shared__ float Ws[BJ][BK + 1];
    const int tid = threadIdx.x;
    const int bt = blockIdx.y * BT;
    const int bj = blockIdx.x * BJ;
    const int tx = tid & 15;
    const int ty = tid >> 4;

    float acc[8][8];
#pragma unroll
    for (int i = 0; i < 8; i++)
#pragma unroll
        for (int j = 0; j < 8; j++) acc[i][j] = 0.f;

    for (int k0 = 0; k0 < IN_DIM; k0 += BK) {
#pragma unroll
        for (int i = tid; i < BT * (BK / 4); i += 128) {
            int t = i / (BK / 4), kq = i % (BK / 4);
            float4 v = *(const float4*)(X + (size_t)(bt + t) * IN_DIM + k0 + kq * 4);
            Xs[t][kq * 4 + 0] = v.x; Xs[t][kq * 4 + 1] = v.y;
            Xs[t][kq * 4 + 2] = v.z; Xs[t][kq * 4 + 3] = v.w;
        }
#pragma unroll
        for (int i = tid; i < BJ * (BK / 4); i += 128) {
            int j = i / (BK / 4), kq = i % (BK / 4);
            float4 v = *(const float4*)(W + (size_t)(bj + j) * IN_DIM + k0 + kq * 4);
            Ws[j][kq * 4 + 0] = v.x; Ws[j][kq * 4 + 1] = v.y;
            Ws[j][kq * 4 + 2] = v.z; Ws[j][kq * 4 + 3] = v.w;
        }
        __syncthreads();
#pragma unroll 8
        for (int kk = 0; kk < BK; kk++) {
            float a[8], b[8];
#pragma unroll
            for (int i = 0; i < 8; i++) a[i] = Xs[ty * 8 + i][kk];
#pragma unroll
            for (int j = 0; j < 8; j++) b[j] = Ws[tx * 8 + j][kk];
#pragma unroll
            for (int i = 0; i < 8; i++)
#pragma unroll
                for (int j = 0; j < 8; j++) acc[i][j] += a[i] * b[j];
        }
        __syncthreads();
    }
#pragma unroll
    for (int i = 0; i < 8; i++) {
        int t = bt + ty * 8 + i;
#pragma unroll
        for (int j = 0; j < 8; j++) {
            int col = bj + tx * 8 + j;
            g_pre1[(size_t)t * H_DIM + col] = acc[i][j] + __ldg(b1 + col) + __ldg(b2 + col);
        }
    }
}

// ---------------------------------------------------------------------------
// Kernel 2: persistent RNN, FUSED phases + REDG barrier. Each barrier-to-
// barrier segment computes BOTH h2(t) and h1(t+1) from one post-barrier load
// of h1(t), h2(t-1). Exactly ONE grid barrier per step.
// Stage-1: 4 xor-shuffles -> 2 partials/warp -> red[28][16] (1792B).
// Stage-2: 28 rows x 8 threads (tid<224), width-8 shfl_down.
// ---------------------------------------------------------------------------
__global__ __launch_bounds__(NTHR, 1) void rnn_persistent(
    const float* __restrict__ W_h2h1,
    const float* __restrict__ W_i2h2,
    const float* __restrict__ b_i2h2,
    const float* __restrict__ W_h2h2,
    const float* __restrict__ b_h2h2)
{
    extern __shared__ float smem[];
    float* Wsh1 = smem;                    // [MAXR][2048]
    float* Wsh2 = smem + MAXR * H_DIM;     // [MAXR][2048]
    __shared__ __align__(8) float red[2 * MAXR][16];   // 1792B
    __shared__ float bsum[MAXR];

    const int tid = threadIdx.x;
    const int bid = blockIdx.x;
    const int r0 = (bid * H_DIM) / GRID_P;
    const int r1 = ((bid + 1) * H_DIM) / GRID_P;
    const int nr = r1 - r0;                // 13 or 14
    const int lane = tid & 31;
    const int wid = tid >> 5;

    // h1(0) = tanh(pre1[0]) (h1(-1)=0); h2(-1) = 0 lives in g_h2[1]
    if (tid < nr) {
        g_h1[0][r0 + tid] = tanhf(__ldg(&g_pre1[r0 + tid]));
        g_h2[1][r0 + tid] = 0.f;
        bsum[tid] = __ldg(b_i2h2 + r0 + tid) + __ldg(b_h2h2 + r0 + tid);
    }

    // SMEM weight caches (own rows of W_h2h1, W_h2h2)
    {
        const float4* s1 = (const float4*)(W_h2h1 + (size_t)r0 * H_DIM);
        const float4* s2 = (const float4*)(W_h2h2 + (size_t)r0 * H_DIM);
        float4* d1 = (float4*)Wsh1;
        float4* d2 = (float4*)Wsh2;
        const int n4 = nr * (H_DIM / 4);
        for (int i = tid; i < n4; i += NTHR) { d1[i] = s1[i]; d2[i] = s2[i]; }
    }

    // Register-stationary W_i2h2 slices (cols 4*tid.. and 1024+4*tid..)
    float4 wr0[MAXR], wr1[MAXR];
#pragma unroll
    for (int rr = 0; rr < MAXR; rr++) {
        int r = (rr < nr) ? (r0 + rr) : r0;
        const float4* wp = (const float4*)(W_i2h2 + (size_t)r * H_DIM);
        wr0[rr] = wp[tid];
        wr1[rr] = wp[tid + 256];
    }

    unsigned tgt = GRID_P;
    grid_bar(tgt);                         // h1(0), h2(-1), caches visible

    const int frow = tid >> 3;             // stage-2 row (0..31)
    const int fs = tid & 7;                // stage-2 sub-index
    // clamped prefetch row for the A-part (rows 14..27 -> pre1 row)
    const int prowA = (frow >= MAXR) ? (((frow - MAXR) < nr) ? (frow - MAXR) : (nr - 1)) : 0;

    for (int t = 0; t < T_SEQ - 1; t++) {
        const int q = t & 1;

        // prefetch pre1[t+1] for the A rows
        float pre = __ldg(&g_pre1[(size_t)(t + 1) * H_DIM + r0 + prowA]);

        // single post-barrier load: h1(t) and h2(t-1) slices
        float4 n0 = __ldcg((const float4*)g_h1[q] + tid);
        float4 n1 = __ldcg((const float4*)g_h1[q] + tid + 256);
        float4 c0 = __ldcg((const float4*)g_h2[1 - q] + tid);
        float4 c1 = __ldcg((const float4*)g_h2[1 - q] + tid + 256);

        // ---- fused stage-1: accB -> h2(t) rows, accA -> h1(t+1) rows ----
#pragma unroll
        for (int rr = 0; rr < MAXR; rr++) {
            const float* w1 = Wsh1 + rr * H_DIM;
            const float* w2 = Wsh2 + rr * H_DIM;
            float4 w10 = *(const float4*)(w1 + 4 * tid);
            float4 w11 = *(const float4*)(w1 + 4 * tid + 1024);
            float4 w20 = *(const float4*)(w2 + 4 * tid);
            float4 w21 = *(const float4*)(w2 + 4 * tid + 1024);
            float accA = dot4(w10, n0) + dot4(w11, n1);
            float accB = dot4(wr0[rr], n0) + dot4(wr1[rr], n1)
                       + dot4(w20, c0) + dot4(w21, c1);
            accA += __shfl_xor_sync(0xffffffffu, accA, 16);
            accB += __shfl_xor_sync(0xffffffffu, accB, 16);
            accA += __shfl_xor_sync(0xffffffffu, accA, 8);
            accB += __shfl_xor_sync(0xffffffffu, accB, 8);
            accA += __shfl_xor_sync(0xffffffffu, accA, 4);
            accB += __shfl_xor_sync(0xffffffffu, accB, 4);
            accA += __shfl_xor_sync(0xffffffffu, accA, 2);
            accB += __shfl_xor_sync(0xffffffffu, accB, 2);
            if (lane < 2) {
                red[rr][wid * 2 + lane] = accB;          // even/odd partials
                red[MAXR + rr][wid * 2 + lane] = accA;
            }
        }
        __syncthreads();

        // ---- stage-2: 28 rows x 8 threads ----
        if (tid < 224) {
            float2 v = *(const float2*)&red[frow][fs * 2];
            float x = v.x + v.y;
            x += __shfl_down_sync(0xffffffffu, x, 4, 8);
            x += __shfl_down_sync(0xffffffffu, x, 2, 8);
            x += __shfl_down_sync(0xffffffffu, x, 1, 8);
            if (fs == 0) {
                if (frow < MAXR) {                       // B: h2(t)
                    if (frow < nr)
                        g_h2[q][r0 + frow] = tanhf(bsum[frow] + x);
                } else {                                 // A: h1(t+1)
                    int ar = frow - MAXR;
                    if (ar < nr)
                        g_h1[1 - q][r0 + ar] = tanhf(pre + x);
                }
            }
        }
        tgt += GRID_P;
        grid_bar(tgt);     // the ONLY grid barrier of the step
    }

    // ---- epilogue t = 511: h2(511) only ----
    {
        float4 n0 = __ldcg((const float4*)g_h1[1] + tid);
        float4 n1 = __ldcg((const float4*)g_h1[1] + tid + 256);
        float4 c0 = __ldcg((const float4*)g_h2[0] + tid);
        float4 c1 = __ldcg((const float4*)g_h2[0] + tid + 256);
#pragma unroll
        for (int rr = 0; rr < MAXR; rr++) {
            const float* w2 = Wsh2 + rr * H_DIM;
            float4 w20 = *(const float4*)(w2 + 4 * tid);
            float4 w21 = *(const float4*)(w2 + 4 * tid + 1024);
            float accB = dot4(wr0[rr], n0) + dot4(wr1[rr], n1)
                       + dot4(w20, c0) + dot4(w21, c1);
            accB += __shfl_xor_sync(0xffffffffu, accB, 16);
            accB += __shfl_xor_sync(0xffffffffu, accB, 8);
            accB += __shfl_xor_sync(0xffffffffu, accB, 4);
            accB += __shfl_xor_sync(0xffffffffu, accB, 2);
            if (lane < 2) red[rr][wid * 2 + lane] = accB;
        }
        __syncthreads();
        if (tid < 224) {
            float2 v = *(const float2*)&red[frow][fs * 2];
            float x = v.x + v.y;
            x += __shfl_down_sync(0xffffffffu, x, 4, 8);
            x += __shfl_down_sync(0xffffffffu, x, 2, 8);
            x += __shfl_down_sync(0xffffffffu, x, 1, 8);
            if (fs == 0 && frow < nr)
                g_h2[1][r0 + frow] = tanhf(bsum[frow] + x);
        }
    }
    // final h2 (t=511) is in g_h2[1]; kernel boundary publishes it
}

// ---------------------------------------------------------------------------
// Kernel 3: out = h2_final @ W_h2o2^T + b_h2o2
// ---------------------------------------------------------------------------
__global__ __launch_bounds__(256) void out_gemv(
    const float* __restrict__ W, const float* __restrict__ b,
    float* __restrict__ out)
{
    const int lane = threadIdx.x & 31;
    const int warp = threadIdx.x >> 5;
    const int row = blockIdx.x * 8 + warp;
    const float4* wp = (const float4*)(W + (size_t)row * H_DIM);
    const float4* hp = (const float4*)g_h2[1];
    float acc = 0.f;
#pragma unroll
    for (int i = 0; i < 16; i++) {
        float4 w4 = __ldg(wp + i * 32 + lane);
        float4 h4 = __ldcg(hp + i * 32 + lane);
        acc += dot4(w4, h4);
    }
#pragma unroll
    for (int off = 16; off; off >>= 1)
        acc += __shfl_xor_sync(0xffffffffu, acc, off);
    if (lane == 0) out[row] = acc + __ldg(b + row);
}

// ---------------------------------------------------------------------------
extern "C" void kernel_launch(void* const* d_in, const int* in_sizes, int n_in,
                              void* d_out, int out_size)
{
    const float* word   = (const float*)d_in[0];
    const float* W_i2h1 = (const float*)d_in[1];
    const float* b_i2h1 = (const float*)d_in[2];
    const float* W_h2h1 = (const float*)d_in[3];
    const float* b_h2h1 = (const float*)d_in[4];
    // d_in[5], d_in[6]: W_h2o1 / b_h2o1 — dead code in reference
    const float* W_i2h2 = (const float*)d_in[7];
    const float* b_i2h2 = (const float*)d_in[8];
    const float* W_h2h2 = (const float*)d_in[9];
    const float* b_h2h2 = (const float*)d_in[10];
    const float* W_h2o2 = (const float*)d_in[11];
    const float* b_h2o2 = (const float*)d_in[12];
    float* out = (float*)d_out;

    cudaFuncSetAttribute(rnn_persistent,
                         cudaFuncAttributeMaxDynamicSharedMemorySize, SMEM_BYTES);

    dim3 pg(H_DIM / BJ, T_SEQ / BT);
    pre_gemm<<<pg, 128>>>(word, W_i2h1, b_i2h1, b_h2h1);
    rnn_persistent<<<GRID_P, NTHR, SMEM_BYTES>>>(W_h2h1, W_i2h2, b_i2h2,
                                                 W_h2h2, b_h2h2);
    out_gemv<<<OUT_DIM / 8, 256>>>(W_h2o2, b_h2o2, out);
}